// round 15
// baseline (speedup 1.0000x reference)
#include <cuda_runtime.h>
#include <cuda_fp16.h>
#include <math.h>
#include <float.h>
#include <stdint.h>

// Problem constants
#define BB   8
#define CQ   1024
#define CR   512
#define HID  256
#define NP   2304          // H*W = 48*48
#define NBLK 18            // NP / 128 p-blocks

#define KC   16            // k per smem stage
#define TPS  68            // T-layout smem words per k-row (64 data + 4 pad)

// ---------------------------------------------------------------------------
// Device-global scratch. "Planes" are fp16 hi/lo pairs packed in u32.
// ---------------------------------------------------------------------------
__device__ uint32_t g_rfS[(size_t)BB * CR * NP / 2];      // [b][c][p] V, single fp16
__device__ uint32_t g_Wq_hi[(size_t)HID * CQ / 2];
__device__ uint32_t g_Wq_lo[(size_t)HID * CQ / 2];
__device__ uint32_t g_Wk_hi[(size_t)HID * CR / 2];
__device__ uint32_t g_Wk_lo[(size_t)HID * CR / 2];
__device__ uint32_t g_Q_hi[(size_t)BB * NP * HID / 2];    // [b][i][o]
__device__ uint32_t g_Q_lo[(size_t)BB * NP * HID / 2];
__device__ uint32_t g_K_hi[(size_t)BB * NP * HID / 2];    // [b][p][o]
__device__ uint32_t g_K_lo[(size_t)BB * NP * HID / 2];
__device__ uint32_t g_at[(size_t)BB * NP * NP / 2];       // [b][i][p] exp(x-lmax), fp16
__device__ float    g_lmax[(size_t)BB * NP * NBLK];       // per (row, p-block) max
__device__ float    g_lsum[(size_t)BB * NP * NBLK];       // per (row, p-block) sum
__device__ float    g_scale[(size_t)BB * NP * NBLK];      // exp(lmax-M)/S

// ---------------------------------------------------------------------------
// helpers
// ---------------------------------------------------------------------------
__device__ __forceinline__ void split_f16(float x, unsigned short &h, unsigned short &l) {
    __half hb = __float2half_rn(x);
    h = __half_as_ushort(hb);
    float r = x - __half2float(hb);
    l = __half_as_ushort(__float2half_rn(r));
}
__device__ __forceinline__ void split_pair_words(float x0, float x1,
                                                 uint32_t &hw, uint32_t &lw) {
    unsigned short h0, l0, h1, l1;
    split_f16(x0, h0, l0);
    split_f16(x1, h1, l1);
    hw = (uint32_t)h0 | ((uint32_t)h1 << 16);
    lw = (uint32_t)l0 | ((uint32_t)l1 << 16);
}
__device__ __forceinline__ uint32_t pack_h2(float x0, float x1) {
    const __half2 h2 = __floats2half2_rn(x0, x1);
    return *(const uint32_t*)&h2;
}

// fp16 inputs, fp32 accumulate
__device__ __forceinline__ void mma_f16(float c[4], const uint32_t a[4],
                                        const uint32_t b0, const uint32_t b1) {
    asm volatile(
        "mma.sync.aligned.m16n8k16.row.col.f32.f16.f16.f32 "
        "{%0,%1,%2,%3}, {%4,%5,%6,%7}, {%8,%9}, {%0,%1,%2,%3};\n"
        : "+f"(c[0]), "+f"(c[1]), "+f"(c[2]), "+f"(c[3])
        : "r"(a[0]), "r"(a[1]), "r"(a[2]), "r"(a[3]),
          "r"(b0), "r"(b1));
}

__device__ __forceinline__ void ldsm4(uint32_t r[4], uint32_t addr) {
    asm volatile("ldmatrix.sync.aligned.m8n8.x4.shared.b16 {%0,%1,%2,%3}, [%4];"
                 : "=r"(r[0]), "=r"(r[1]), "=r"(r[2]), "=r"(r[3]) : "r"(addr));
}
__device__ __forceinline__ void ldsm4t(uint32_t r[4], uint32_t addr) {
    asm volatile("ldmatrix.sync.aligned.m8n8.x4.trans.shared.b16 {%0,%1,%2,%3}, [%4];"
                 : "=r"(r[0]), "=r"(r[1]), "=r"(r[2]), "=r"(r[3]) : "r"(addr));
}
__device__ __forceinline__ void ldsm2(uint32_t r[2], uint32_t addr) {
    asm volatile("ldmatrix.sync.aligned.m8n8.x2.shared.b16 {%0,%1}, [%2];"
                 : "=r"(r[0]), "=r"(r[1]) : "r"(addr));
}
__device__ __forceinline__ void cpasync16(uint32_t saddr, const void* g) {
    asm volatile("cp.async.cg.shared.global [%0], [%1], 16;" :: "r"(saddr), "l"(g));
}
#define CP_COMMIT() asm volatile("cp.async.commit_group;" ::: "memory")
#define CP_WAIT0()  asm volatile("cp.async.wait_group 0;" ::: "memory")
#define CP_WAIT1()  asm volatile("cp.async.wait_group 1;" ::: "memory")

// ---------------------------------------------------------------------------
// Elementwise split: fp32 -> hi/lo fp16 planes (pairs packed in u32).
// ---------------------------------------------------------------------------
__global__ void __launch_bounds__(256) split_pairs(
    const float* __restrict__ src,
    uint32_t* __restrict__ dhi, uint32_t* __restrict__ dlo, size_t npairs)
{
    size_t i = (size_t)blockIdx.x * 256 + threadIdx.x;
    if (i >= npairs) return;
    uint32_t hw, lw;
    split_pair_words(src[2 * i], src[2 * i + 1], hw, lw);
    dhi[i] = hw;
    dlo[i] = lw;
}

// ---------------------------------------------------------------------------
// Elementwise convert: fp32 -> single fp16 plane (pairs packed in u32).
// ---------------------------------------------------------------------------
__global__ void __launch_bounds__(256) cvt_pairs(
    const float* __restrict__ src,
    uint32_t* __restrict__ dst, size_t npairs)
{
    size_t i = (size_t)blockIdx.x * 256 + threadIdx.x;
    if (i >= npairs) return;
    dst[i] = pack_h2(src[2 * i], src[2 * i + 1]);
}

// ---------------------------------------------------------------------------
// Split-fp16 tensor-core GEMM.
//   C[m][n] = sum_k A[m][k] * B[n][k]
// 128x128 CTA tile, 256 threads, 8 warps = 2(m) x 4(n), warp tile 64x32.
// AMODE: 0 = A hi/lo planes R-layout, 1 = A single plane R-layout,
//        2 = A fp32 [k][m] source (fused transpose+split, 2-stage).
// AMODE 0/1 use a 3-stage cp.async ring with wait_group 1 so loads have a
// full chunk of slack and the per-chunk barrier is near-free.
// BSINGLE: B single fp16 plane. OMODE: 0 fp32 / 1 split / 2 flash softmax.
// BSCALE: B fragments scaled inline by per-(n, kblock) softmax scales.
// Dynamic smem: [STAGES*ASTAGE | STAGES*BSTAGE] words.
// ---------------------------------------------------------------------------
template<bool BIAS, int OMODE, int AMODE, bool BSINGLE, bool BSCALE>
__global__ void __launch_bounds__(256, 2) bgemm(
    const uint32_t* __restrict__ Ahi32, const uint32_t* __restrict__ Alo32,
    int lda, size_t sA,
    const uint32_t* __restrict__ Bhi32, const uint32_t* __restrict__ Blo32,
    int ldb, size_t sB,
    const float* __restrict__ bias,
    float* __restrict__ C, uint32_t* __restrict__ Chi, uint32_t* __restrict__ Clo,
    int ldc, size_t sC, int Ktot,
    float* __restrict__ lmax_out, float* __restrict__ lsum_out,
    const float* __restrict__ bscale)
{
    constexpr int STAGES = (AMODE == 2) ? 2 : 3;
    constexpr int ASTAGE = (AMODE == 2) ? (2 * KC * TPS)
                         : (AMODE == 1) ? (128 * 12) : (128 * 20);
    constexpr int BPS = BSINGLE ? 12 : 20;
    constexpr int BSTAGE = 128 * BPS;
    extern __shared__ uint32_t dsm[];
    uint32_t* Asm = dsm;
    uint32_t* Bsm = dsm + STAGES * ASTAGE;
    __shared__ float red[OMODE == 2 ? 4 : 1][OMODE == 2 ? 128 : 1];
    __shared__ float sscale[BSCALE ? 128 * NBLK : 1];

    const int bz = blockIdx.z;
    const int tid = threadIdx.x;
    const int m0  = blockIdx.x * 128;
    const int n0  = blockIdx.y * 128;

    // ---- B loader (cp.async): thread -> (row, plane); 2x16B per plane/stage
    const __half* Bhi = (const __half*)Bhi32 + sB * bz;
    const __half* Blo = (const __half*)Blo32 + sB * bz;
    const int lrow = tid >> 1;
    const int lpl  = tid & 1;
    const __half* Bsrc = ((lpl && !BSINGLE) ? Blo : Bhi) + (size_t)(n0 + lrow) * ldb;
    const bool   bload = (!BSINGLE) || (lpl == 0);
    const uint32_t sdstB = (uint32_t)(lrow * BPS + lpl * 8) * 4;

    // ---- A loader ----
    const __half* Ahi = (const __half*)Ahi32 + sA * bz;
    const __half* Alo = (const __half*)Alo32 + sA * bz;
    const __half* Asrc = ((lpl && AMODE == 0) ? Alo : Ahi) + (size_t)(m0 + lrow) * lda;
    const bool   aload = (AMODE == 0) || (lpl == 0);
    constexpr int APS = (AMODE == 1) ? 12 : 20;
    const uint32_t sdstA = (uint32_t)(lrow * APS + lpl * 8) * 4;
    // AMODE 2 (fp32 [k][m] LDG + split)
    const float* Af = (const float*)Ahi32 + sA * bz;
    const int tkr = tid >> 4;
    const int tmc = (tid & 15) * 8;
    const float* Ag = Af + (size_t)tkr * lda + m0 + tmc;
    const uint32_t sdstT = (uint32_t)(tkr * TPS + (tid & 15) * 4) * 4;

    const uint32_t aS = (uint32_t)__cvta_generic_to_shared(Asm);
    const uint32_t bS = (uint32_t)__cvta_generic_to_shared(Bsm);
    const uint32_t stageA = ASTAGE * 4;
    const uint32_t stageB = BSTAGE * 4;

    // warp/lane decomposition
    const int wid = tid >> 5, lane = tid & 31;
    const int wm = (wid & 1) * 64;
    const int wn = (wid >> 1) * 32;
    const int qr = lane >> 2, qc = lane & 3;

    // ldmatrix per-lane addresses (byte offsets within a stage)
    uint32_t aoff[4], boff[4];
    {
        if (AMODE == 2) {
            const int krl = (lane & 7) + ((lane & 16) ? 8 : 0);
            const int mcl = (lane & 8) ? 8 : 0;
            #pragma unroll
            for (int mt = 0; mt < 4; mt++)
                aoff[mt] = (uint32_t)(krl * TPS * 4 + (wm + mt * 16 + mcl) * 2);
        } else {
            const int arl = (lane & 7) + (lane & 8);
            const int awd = (lane & 16) ? 4 : 0;
            #pragma unroll
            for (int mt = 0; mt < 4; mt++)
                aoff[mt] = (uint32_t)(((wm + mt * 16 + arl) * APS + awd) * 4);
        }
        const int brl = lane & 7;
        const int bwd = BSINGLE ? (((lane >> 3) & 1) * 4)
                                : (((lane >> 3) & 3) * 4);
        #pragma unroll
        for (int nt = 0; nt < 4; nt++)
            boff[nt] = (uint32_t)(((wn + nt * 8 + brl) * BPS + bwd) * 4);
    }

    if (BSCALE) {
        const size_t sb0 = ((size_t)bz * (size_t)(gridDim.y * 128) + n0) * NBLK;
        for (int idx = tid; idx < 128 * NBLK; idx += 256)
            sscale[idx] = bscale[sb0 + idx];
    }

    float acc[4][4][4];
    #pragma unroll
    for (int mt = 0; mt < 4; mt++)
        #pragma unroll
        for (int nt = 0; nt < 4; nt++)
            #pragma unroll
            for (int r = 0; r < 4; r++) acc[mt][nt][r] = 0.f;

    const int nk = Ktot / KC;

    // issue cp.async loads for one chunk into stage s (AMODE 0/1 + B)
    auto issue_loads = [&](int chunk, int s) {
        const int k0 = chunk * KC;
        if (AMODE != 2 && aload) {
            const uint32_t ad = aS + (uint32_t)s * stageA + sdstA;
            cpasync16(ad,      Asrc + k0);
            cpasync16(ad + 16, Asrc + k0 + 8);
        }
        if (bload) {
            const uint32_t bd = bS + (uint32_t)s * stageB + sdstB;
            cpasync16(bd,      Bsrc + k0);
            cpasync16(bd + 16, Bsrc + k0 + 8);
        }
        CP_COMMIT();
    };

    // T-layout STS helper for AMODE2
    auto sts_trans = [&](int s, float4 v0, float4 v1) {
        uint32_t h[4], l[4];
        split_pair_words(v0.x, v0.y, h[0], l[0]);
        split_pair_words(v0.z, v0.w, h[1], l[1]);
        split_pair_words(v1.x, v1.y, h[2], l[2]);
        split_pair_words(v1.z, v1.w, h[3], l[3]);
        uint32_t* hp = Asm + s * ASTAGE + (sdstT >> 2);
        *(uint4*)hp              = make_uint4(h[0], h[1], h[2], h[3]);
        *(uint4*)(hp + KC * TPS) = make_uint4(l[0], l[1], l[2], l[3]);
    };

    // per-chunk compute on stage buffers (ab, bb = byte bases)
    auto compute_chunk = [&](int kb, uint32_t ab, uint32_t bb) {
        uint32_t ah[4][4], al[4][4];
        #pragma unroll
        for (int mt = 0; mt < 4; mt++) {
            if (AMODE == 2) {
                ldsm4t(ah[mt], ab + aoff[mt]);
                ldsm4t(al[mt], ab + aoff[mt] + KC * TPS * 4);
            } else {
                ldsm4(ah[mt], ab + aoff[mt]);
                if (AMODE == 0)
                    ldsm4(al[mt], ab + aoff[mt] + 32);
            }
        }
        #pragma unroll
        for (int nt = 0; nt < 4; nt++) {
            if (BSINGLE) {
                uint32_t bv[2];
                ldsm2(bv, bb + boff[nt]);
                if (BSCALE) {
                    const float s = sscale[(wn + nt * 8 + (lane >> 2)) * NBLK + (kb >> 3)];
                    const __half2 hs = __float2half2_rn(s);
                    *(__half2*)&bv[0] = __hmul2(*(const __half2*)&bv[0], hs);
                    *(__half2*)&bv[1] = __hmul2(*(const __half2*)&bv[1], hs);
                }
                if (AMODE != 1) {
                    #pragma unroll
                    for (int mt = 0; mt < 4; mt++)
                        mma_f16(acc[mt][nt], al[mt], bv[0], bv[1]);
                }
                #pragma unroll
                for (int mt = 0; mt < 4; mt++)
                    mma_f16(acc[mt][nt], ah[mt], bv[0], bv[1]);
            } else {
                uint32_t bv[4];
                ldsm4(bv, bb + boff[nt]);
                if (AMODE != 1) {
                    #pragma unroll
                    for (int mt = 0; mt < 4; mt++)
                        mma_f16(acc[mt][nt], ah[mt], bv[2], bv[3]);   // ah*bl
                    #pragma unroll
                    for (int mt = 0; mt < 4; mt++)
                        mma_f16(acc[mt][nt], al[mt], bv[0], bv[1]);   // al*bh
                    #pragma unroll
                    for (int mt = 0; mt < 4; mt++)
                        mma_f16(acc[mt][nt], ah[mt], bv[0], bv[1]);   // ah*bh
                } else {
                    #pragma unroll
                    for (int mt = 0; mt < 4; mt++)
                        mma_f16(acc[mt][nt], ah[mt], bv[2], bv[3]);
                    #pragma unroll
                    for (int mt = 0; mt < 4; mt++)
                        mma_f16(acc[mt][nt], ah[mt], bv[0], bv[1]);
                }
            }
        }
    };

    if (STAGES == 2) {
        // ---- AMODE2: 2-stage, register-staged fp32 A transpose + cp.async B
        {
            float4 v0 = *(const float4*)Ag;
            float4 v1 = *(const float4*)(Ag + 4);
            sts_trans(0, v0, v1);
            issue_loads(0, 0);
            CP_WAIT0();
            __syncthreads();
        }
        int buf = 0;
        for (int kb = 0; kb < nk; kb++) {
            const bool has_next = (kb + 1) < nk;
            float4 av0, av1;
            if (has_next) {
                const float* p = Ag + (size_t)(kb + 1) * KC * lda;
                av0 = *(const float4*)p;
                av1 = *(const float4*)(p + 4);
                issue_loads(kb + 1, buf ^ 1);
            }
            compute_chunk(kb, aS + buf * stageA, bS + buf * stageB);
            if (has_next) {
                sts_trans(buf ^ 1, av0, av1);
                CP_WAIT0();
                __syncthreads();
                buf ^= 1;
            }
        }
    } else {
        // ---- AMODE 0/1: 3-stage cp.async ring, wait_group 1
        issue_loads(0, 0);
        if (nk > 1) issue_loads(1, 1);
        for (int kb = 0; kb < nk; kb++) {
            if (kb + 1 < nk) { CP_WAIT1(); } else { CP_WAIT0(); }
            __syncthreads();
            if (kb + 2 < nk) issue_loads(kb + 2, (kb + 2) % 3);
            const int s = kb % 3;
            compute_chunk(kb, aS + s * stageA, bS + s * stageB);
        }
    }

    // ---- epilogue ----
    if (OMODE == 2) {
        const int wni = wid >> 1;
        float rmax[8];
        #pragma unroll
        for (int j = 0; j < 8; j++) rmax[j] = -FLT_MAX;
        #pragma unroll
        for (int mt = 0; mt < 4; mt++)
            #pragma unroll
            for (int nt = 0; nt < 4; nt++) {
                rmax[mt * 2 + 0] = fmaxf(rmax[mt * 2 + 0],
                                         fmaxf(acc[mt][nt][0], acc[mt][nt][1]));
                rmax[mt * 2 + 1] = fmaxf(rmax[mt * 2 + 1],
                                         fmaxf(acc[mt][nt][2], acc[mt][nt][3]));
            }
        #pragma unroll
        for (int j = 0; j < 8; j++) {
            rmax[j] = fmaxf(rmax[j], __shfl_xor_sync(0xffffffffu, rmax[j], 1));
            rmax[j] = fmaxf(rmax[j], __shfl_xor_sync(0xffffffffu, rmax[j], 2));
        }
        if (qc == 0)
            #pragma unroll
            for (int mt = 0; mt < 4; mt++)
                #pragma unroll
                for (int h = 0; h < 2; h++)
                    red[wni][wm + mt * 16 + qr + 8 * h] = rmax[mt * 2 + h];
        __syncthreads();
        float fm[8];
        #pragma unroll
        for (int mt = 0; mt < 4; mt++)
            #pragma unroll
            for (int h = 0; h < 2; h++) {
                const int rl = wm + mt * 16 + qr + 8 * h;
                fm[mt * 2 + h] = fmaxf(fmaxf(red[0][rl], red[1][rl]),
                                       fmaxf(red[2][rl], red[3][rl]));
            }
        __syncthreads();

        float rs[8];
        #pragma unroll
        for (int j = 0; j < 8; j++) rs[j] = 0.f;
        uint32_t* chb = Chi + (size_t)bz * (sC >> 1);
        #pragma unroll
        for (int mt = 0; mt < 4; mt++)
            #pragma unroll
            for (int nt = 0; nt < 4; nt++) {
                const int col = n0 + wn + nt * 8 + 2 * qc;
                #pragma unroll
                for (int h = 0; h < 2; h++) {
                    const float e0 = __expf(acc[mt][nt][2 * h + 0] - fm[mt * 2 + h]);
                    const float e1 = __expf(acc[mt][nt][2 * h + 1] - fm[mt * 2 + h]);
                    const int row = m0 + wm + mt * 16 + qr + 8 * h;
                    chb[(size_t)row * (ldc >> 1) + (col >> 1)] = pack_h2(e0, e1);
                    rs[mt * 2 + h] += e0 + e1;
                }
            }
        #pragma unroll
        for (int j = 0; j < 8; j++) {
            rs[j] += __shfl_xor_sync(0xffffffffu, rs[j], 1);
            rs[j] += __shfl_xor_sync(0xffffffffu, rs[j], 2);
        }
        if (qc == 0)
            #pragma unroll
            for (int mt = 0; mt < 4; mt++)
                #pragma unroll
                for (int h = 0; h < 2; h++)
                    red[wni][wm + mt * 16 + qr + 8 * h] = rs[mt * 2 + h];
        __syncthreads();
        if (wni == 0 && qc == 0) {
            const size_t mtot = (size_t)gridDim.x * 128;
            #pragma unroll
            for (int mt = 0; mt < 4; mt++)
                #pragma unroll
                for (int h = 0; h < 2; h++) {
                    const int rl = wm + mt * 16 + qr + 8 * h;
                    const float sm = red[0][rl] + red[1][rl] + red[2][rl] + red[3][rl];
                    const size_t o = ((size_t)bz * mtot + m0 + rl) * NBLK + blockIdx.y;
                    lmax_out[o] = fm[mt * 2 + h];
                    lsum_out[o] = sm;
                }
        }
    } else {
        #pragma unroll
        for (int mt = 0; mt < 4; mt++) {
            #pragma unroll
            for (int nt = 0; nt < 4; nt++) {
                const int row = m0 + wm + mt * 16 + qr;
                const int col = n0 + wn + nt * 8 + 2 * qc;
                float v0 = acc[mt][nt][0], v1 = acc[mt][nt][1];
                float v2 = acc[mt][nt][2], v3 = acc[mt][nt][3];
                if (BIAS) {
                    const float b0 = bias[col], b1 = bias[col + 1];
                    v0 += b0; v1 += b1; v2 += b0; v3 += b1;
                }
                if (OMODE == 1) {
                    uint32_t* chb = Chi + (size_t)bz * (sC >> 1);
                    uint32_t* clb = Clo + (size_t)bz * (sC >> 1);
                    uint32_t hw, lw;
                    split_pair_words(v0, v1, hw, lw);
                    size_t o = (size_t)row * (ldc >> 1) + (col >> 1);
                    chb[o] = hw; clb[o] = lw;
                    split_pair_words(v2, v3, hw, lw);
                    o = (size_t)(row + 8) * (ldc >> 1) + (col >> 1);
                    chb[o] = hw; clb[o] = lw;
                } else {
                    float* cb = C + sC * bz;
                    *(float2*)&cb[(size_t)row * ldc + col]       = make_float2(v0, v1);
                    *(float2*)&cb[(size_t)(row + 8) * ldc + col] = make_float2(v2, v3);
                }
            }
        }
    }
}

// ---------------------------------------------------------------------------
// Combine per-block softmax stats -> per-(row, block) scale = exp(lmax-M)/S.
// ---------------------------------------------------------------------------
__global__ void __launch_bounds__(256) combine_stats(
    const float* __restrict__ lmax, const float* __restrict__ lsum,
    float* __restrict__ scale)
{
    const int r = blockIdx.x * 256 + threadIdx.x;
    if (r >= BB * NP) return;
    const float* lm = lmax + (size_t)r * NBLK;
    const float* ls = lsum + (size_t)r * NBLK;
    float M = -FLT_MAX;
    #pragma unroll
    for (int j = 0; j < NBLK; j++) M = fmaxf(M, lm[j]);
    float e[NBLK], S = 0.f;
    #pragma unroll
    for (int j = 0; j < NBLK; j++) {
        e[j] = __expf(lm[j] - M);
        S += ls[j] * e[j];
    }
    const float inv = 1.0f / S;
    float* sc = scale + (size_t)r * NBLK;
    #pragma unroll
    for (int j = 0; j < NBLK; j++) sc[j] = e[j] * inv;
}

// ---------------------------------------------------------------------------
extern "C" void kernel_launch(void* const* d_in, const int* in_sizes, int n_in,
                              void* d_out, int out_size)
{
    const float* qf = (const float*)d_in[0];   // [B, CQ, 48, 48]
    const float* rf = (const float*)d_in[1];   // [B, CR, 48, 48]
    const float* Wq = (const float*)d_in[2];   // [HID, CQ]
    const float* bq = (const float*)d_in[3];   // [HID]
    const float* Wk = (const float*)d_in[4];   // [HID, CR]
    const float* bk = (const float*)d_in[5];   // [HID]
    float* out = (float*)d_out;                // [B, CR, 48, 48]

    uint32_t *rfS, *Wqh, *Wql, *Wkh, *Wkl, *Qh, *Ql, *Kh, *Kl, *ath;
    float *lmx, *lsm, *scl;
    cudaGetSymbolAddress((void**)&rfS, g_rfS);
    cudaGetSymbolAddress((void**)&Wqh, g_Wq_hi);
    cudaGetSymbolAddress((void**)&Wql, g_Wq_lo);
    cudaGetSymbolAddress((void**)&Wkh, g_Wk_hi);
    cudaGetSymbolAddress((void**)&Wkl, g_Wk_lo);
    cudaGetSymbolAddress((void**)&Qh, g_Q_hi);
    cudaGetSymbolAddress((void**)&Ql, g_Q_lo);
    cudaGetSymbolAddress((void**)&Kh, g_K_hi);
    cudaGetSymbolAddress((void**)&Kl, g_K_lo);
    cudaGetSymbolAddress((void**)&ath, g_at);
    cudaGetSymbolAddress((void**)&lmx, g_lmax);
    cudaGetSymbolAddress((void**)&lsm, g_lsum);
    cudaGetSymbolAddress((void**)&scl, g_scale);

    // dynamic smem sizes (bytes)
    const int smem12 = (2 * (2 * KC * TPS) + 2 * (128 * 20)) * 4;   // 37888
    const int smem3  = (3 * (128 * 20) * 2) * 4;                    // 61440
    const int smem4  = (3 * (128 * 12) * 2) * 4;                    // 36864
    cudaFuncSetAttribute(bgemm<true, 1, 2, false, false>,
                         cudaFuncAttributeMaxDynamicSharedMemorySize, smem12);
    cudaFuncSetAttribute(bgemm<false, 2, 0, false, false>,
                         cudaFuncAttributeMaxDynamicSharedMemorySize, smem3);
    cudaFuncSetAttribute(bgemm<false, 0, 1, true, true>,
                         cudaFuncAttributeMaxDynamicSharedMemorySize, smem4);

    // ---- prepass: weight splits + V convert ----
    {
        size_t np;
        np = (size_t)HID * CQ / 2;
        split_pairs<<<(unsigned)((np + 255) / 256), 256>>>(Wq, Wqh, Wql, np);
        np = (size_t)HID * CR / 2;
        split_pairs<<<(unsigned)((np + 255) / 256), 256>>>(Wk, Wkh, Wkl, np);
        np = (size_t)BB * CR * NP / 2;
        cvt_pairs<<<(unsigned)((np + 255) / 256), 256>>>(rf, rfS, np);
    }

    // ---- GEMM1: Q[i][o] = qf[c][i] * Wq[o][c] + bq (fused transpose A) ----
    bgemm<true, 1, 2, false, false><<<dim3(NP / 128, HID / 128, BB), 256, smem12>>>(
        (const uint32_t*)qf, nullptr, NP, (size_t)CQ * NP,
        Wqh, Wql, CQ, 0,
        bq,
        nullptr, Qh, Ql, HID, (size_t)NP * HID,
        CQ, nullptr, nullptr, nullptr);

    // ---- GEMM2: K[p][o] = rf[c][p] * Wk[o][c] + bk ----
    bgemm<true, 1, 2, false, false><<<dim3(NP / 128, HID / 128, BB), 256, smem12>>>(
        (const uint32_t*)rf, nullptr, NP, (size_t)CR * NP,
        Wkh, Wkl, CR, 0,
        bk,
        nullptr, Kh, Kl, HID, (size_t)NP * HID,
        CR, nullptr, nullptr, nullptr);

    // ---- GEMM3: S[i][p] = Q[i][k] * K[p][k]; flash epilogue (3-stage) ----
    bgemm<false, 2, 0, false, false><<<dim3(NP / 128, NP / 128, BB), 256, smem3>>>(
        Qh, Ql, HID, (size_t)NP * HID,
        Kh, Kl, HID, (size_t)NP * HID,
        nullptr,
        nullptr, ath, nullptr, NP, (size_t)NP * NP,
        HID, lmx, lsm, nullptr);

    // ---- combine per-block stats -> scales ----
    combine_stats<<<(BB * NP + 255) / 256, 256>>>(lmx, lsm, scl);

    // ---- GEMM4: out[c][i] = V[c][p] * exp[i][p] * scale[i][blk(p)] (3-stage) ----
    bgemm<false, 0, 1, true, true><<<dim3(CR / 128, NP / 128, BB), 256, smem4>>>(
        rfS, rfS, NP, (size_t)CR * NP,
        ath, ath, NP, (size_t)NP * NP,
        nullptr,
        out, nullptr, nullptr, NP, (size_t)CR * NP,
        NP, nullptr, nullptr, scl);
}

// round 16
// speedup vs baseline: 1.0139x; 1.0139x over previous
#include <cuda_runtime.h>
#include <cuda_fp16.h>
#include <math.h>
#include <float.h>
#include <stdint.h>

// Problem constants
#define BB   8
#define CQ   1024
#define CR   512
#define HID  256
#define NP   2304          // H*W = 48*48
#define NBLK 18            // NP / 128 p-blocks

#define KC   16            // k per smem stage
#define TPS  68            // T-layout smem words per k-row (64 data + 4 pad)

// ---------------------------------------------------------------------------
// Device-global scratch. "Planes" are fp16 hi/lo pairs packed in u32.
// ---------------------------------------------------------------------------
__device__ uint32_t g_rfS[(size_t)BB * CR * NP / 2];      // [b][c][p] V, single fp16
__device__ uint32_t g_Wq_hi[(size_t)HID * CQ / 2];
__device__ uint32_t g_Wq_lo[(size_t)HID * CQ / 2];
__device__ uint32_t g_Wk_hi[(size_t)HID * CR / 2];
__device__ uint32_t g_Wk_lo[(size_t)HID * CR / 2];
__device__ uint32_t g_Q_hi[(size_t)BB * NP * HID / 2];    // [b][i][o]
__device__ uint32_t g_Q_lo[(size_t)BB * NP * HID / 2];
__device__ uint32_t g_K_hi[(size_t)BB * NP * HID / 2];    // [b][p][o]
__device__ uint32_t g_K_lo[(size_t)BB * NP * HID / 2];
__device__ uint32_t g_at[(size_t)BB * NP * NP / 2];       // [b][i][p] exp(x-lmax), fp16
__device__ float    g_lmax[(size_t)BB * NP * NBLK];       // per (row, p-block) max
__device__ float    g_lsum[(size_t)BB * NP * NBLK];       // per (row, p-block) sum

// ---------------------------------------------------------------------------
// helpers
// ---------------------------------------------------------------------------
__device__ __forceinline__ void split_f16(float x, unsigned short &h, unsigned short &l) {
    __half hb = __float2half_rn(x);
    h = __half_as_ushort(hb);
    float r = x - __half2float(hb);
    l = __half_as_ushort(__float2half_rn(r));
}
__device__ __forceinline__ void split_pair_words(float x0, float x1,
                                                 uint32_t &hw, uint32_t &lw) {
    unsigned short h0, l0, h1, l1;
    split_f16(x0, h0, l0);
    split_f16(x1, h1, l1);
    hw = (uint32_t)h0 | ((uint32_t)h1 << 16);
    lw = (uint32_t)l0 | ((uint32_t)l1 << 16);
}
__device__ __forceinline__ uint32_t pack_h2(float x0, float x1) {
    const __half2 h2 = __floats2half2_rn(x0, x1);
    return *(const uint32_t*)&h2;
}

// fp16 inputs, fp32 accumulate
__device__ __forceinline__ void mma_f16(float c[4], const uint32_t a[4],
                                        const uint32_t b0, const uint32_t b1) {
    asm volatile(
        "mma.sync.aligned.m16n8k16.row.col.f32.f16.f16.f32 "
        "{%0,%1,%2,%3}, {%4,%5,%6,%7}, {%8,%9}, {%0,%1,%2,%3};\n"
        : "+f"(c[0]), "+f"(c[1]), "+f"(c[2]), "+f"(c[3])
        : "r"(a[0]), "r"(a[1]), "r"(a[2]), "r"(a[3]),
          "r"(b0), "r"(b1));
}

__device__ __forceinline__ void ldsm4(uint32_t r[4], uint32_t addr) {
    asm volatile("ldmatrix.sync.aligned.m8n8.x4.shared.b16 {%0,%1,%2,%3}, [%4];"
                 : "=r"(r[0]), "=r"(r[1]), "=r"(r[2]), "=r"(r[3]) : "r"(addr));
}
__device__ __forceinline__ void ldsm4t(uint32_t r[4], uint32_t addr) {
    asm volatile("ldmatrix.sync.aligned.m8n8.x4.trans.shared.b16 {%0,%1,%2,%3}, [%4];"
                 : "=r"(r[0]), "=r"(r[1]), "=r"(r[2]), "=r"(r[3]) : "r"(addr));
}
__device__ __forceinline__ void ldsm2(uint32_t r[2], uint32_t addr) {
    asm volatile("ldmatrix.sync.aligned.m8n8.x2.shared.b16 {%0,%1}, [%2];"
                 : "=r"(r[0]), "=r"(r[1]) : "r"(addr));
}
__device__ __forceinline__ void cpasync16(uint32_t saddr, const void* g) {
    asm volatile("cp.async.cg.shared.global [%0], [%1], 16;" :: "r"(saddr), "l"(g));
}
#define CP_COMMIT() asm volatile("cp.async.commit_group;" ::: "memory")
#define CP_WAIT0()  asm volatile("cp.async.wait_group 0;" ::: "memory")
#define CP_WAIT1()  asm volatile("cp.async.wait_group 1;" ::: "memory")

// ---------------------------------------------------------------------------
// Elementwise split: fp32 -> hi/lo fp16 planes (pairs packed in u32).
// ---------------------------------------------------------------------------
__global__ void __launch_bounds__(256) split_pairs(
    const float* __restrict__ src,
    uint32_t* __restrict__ dhi, uint32_t* __restrict__ dlo, size_t npairs)
{
    size_t i = (size_t)blockIdx.x * 256 + threadIdx.x;
    if (i >= npairs) return;
    uint32_t hw, lw;
    split_pair_words(src[2 * i], src[2 * i + 1], hw, lw);
    dhi[i] = hw;
    dlo[i] = lw;
}

// ---------------------------------------------------------------------------
// Elementwise convert: fp32 -> single fp16 plane (pairs packed in u32).
// ---------------------------------------------------------------------------
__global__ void __launch_bounds__(256) cvt_pairs(
    const float* __restrict__ src,
    uint32_t* __restrict__ dst, size_t npairs)
{
    size_t i = (size_t)blockIdx.x * 256 + threadIdx.x;
    if (i >= npairs) return;
    dst[i] = pack_h2(src[2 * i], src[2 * i + 1]);
}

// ---------------------------------------------------------------------------
// Split-fp16 tensor-core GEMM.
//   C[m][n] = sum_k A[m][k] * B[n][k]
// 128x128 CTA tile, 256 threads, 8 warps = 2(m) x 4(n), warp tile 64x32.
// AMODE: 0 = A hi/lo planes R-layout (3-stage cp.async ring, dynamic smem),
//        1 = A single plane R-layout (3-stage ring, dynamic smem),
//        2 = A fp32 [k][m] source (fused transpose+split, 2-stage STATIC smem
//            — the R14-measured best config for the projection GEMMs).
// BSINGLE: B single fp16 plane. OMODE: 0 fp32 / 1 split / 2 flash softmax.
// BSCALE: softmax scales computed IN-KERNEL from lmax/lsum stats (per CTA,
//         128 rows x NBLK), applied to B fragments inline.
// ---------------------------------------------------------------------------
template<bool BIAS, int OMODE, int AMODE, bool BSINGLE, bool BSCALE>
__global__ void __launch_bounds__(256, 2) bgemm(
    const uint32_t* __restrict__ Ahi32, const uint32_t* __restrict__ Alo32,
    int lda, size_t sA,
    const uint32_t* __restrict__ Bhi32, const uint32_t* __restrict__ Blo32,
    int ldb, size_t sB,
    const float* __restrict__ bias,
    float* __restrict__ C, uint32_t* __restrict__ Chi, uint32_t* __restrict__ Clo,
    int ldc, size_t sC, int Ktot,
    float* __restrict__ lmax_io, float* __restrict__ lsum_io)
{
    constexpr int STAGES = (AMODE == 2) ? 2 : 3;
    constexpr int ASTAGE = (AMODE == 2) ? (2 * KC * TPS)
                         : (AMODE == 1) ? (128 * 12) : (128 * 20);
    constexpr int BPS = BSINGLE ? 12 : 20;
    constexpr int BSTAGE = 128 * BPS;

    // AMODE2 uses static smem (proven faster); AMODE 0/1 use dynamic smem.
    __shared__ uint32_t Ast[(AMODE == 2) ? (STAGES * ASTAGE) : 1];
    __shared__ uint32_t Bst[(AMODE == 2) ? (STAGES * BSTAGE) : 1];
    extern __shared__ uint32_t dsm[];
    uint32_t* Asm = (AMODE == 2) ? Ast : dsm;
    uint32_t* Bsm = (AMODE == 2) ? Bst : (dsm + STAGES * ASTAGE);
    __shared__ float red[OMODE == 2 ? 4 : 1][OMODE == 2 ? 128 : 1];
    __shared__ float sscale[BSCALE ? 128 * NBLK : 1];

    const int bz = blockIdx.z;
    const int tid = threadIdx.x;
    const int m0  = blockIdx.x * 128;
    const int n0  = blockIdx.y * 128;

    // ---- B loader (cp.async): thread -> (row, plane); 2x16B per plane/stage
    const __half* Bhi = (const __half*)Bhi32 + sB * bz;
    const __half* Blo = (const __half*)Blo32 + sB * bz;
    const int lrow = tid >> 1;
    const int lpl  = tid & 1;
    const __half* Bsrc = ((lpl && !BSINGLE) ? Blo : Bhi) + (size_t)(n0 + lrow) * ldb;
    const bool   bload = (!BSINGLE) || (lpl == 0);
    const uint32_t sdstB = (uint32_t)(lrow * BPS + lpl * 8) * 4;

    // ---- A loader ----
    const __half* Ahi = (const __half*)Ahi32 + sA * bz;
    const __half* Alo = (const __half*)Alo32 + sA * bz;
    const __half* Asrc = ((lpl && AMODE == 0) ? Alo : Ahi) + (size_t)(m0 + lrow) * lda;
    const bool   aload = (AMODE == 0) || (lpl == 0);
    constexpr int APS = (AMODE == 1) ? 12 : 20;
    const uint32_t sdstA = (uint32_t)(lrow * APS + lpl * 8) * 4;
    // AMODE 2 (fp32 [k][m] LDG + split)
    const float* Af = (const float*)Ahi32 + sA * bz;
    const int tkr = tid >> 4;
    const int tmc = (tid & 15) * 8;
    const float* Ag = Af + (size_t)tkr * lda + m0 + tmc;
    const uint32_t sdstT = (uint32_t)(tkr * TPS + (tid & 15) * 4) * 4;

    const uint32_t aS = (uint32_t)__cvta_generic_to_shared(Asm);
    const uint32_t bS = (uint32_t)__cvta_generic_to_shared(Bsm);
    const uint32_t stageA = ASTAGE * 4;
    const uint32_t stageB = BSTAGE * 4;

    // warp/lane decomposition
    const int wid = tid >> 5, lane = tid & 31;
    const int wm = (wid & 1) * 64;
    const int wn = (wid >> 1) * 32;
    const int qr = lane >> 2, qc = lane & 3;

    // ldmatrix per-lane addresses (byte offsets within a stage)
    uint32_t aoff[4], boff[4];
    {
        if (AMODE == 2) {
            const int krl = (lane & 7) + ((lane & 16) ? 8 : 0);
            const int mcl = (lane & 8) ? 8 : 0;
            #pragma unroll
            for (int mt = 0; mt < 4; mt++)
                aoff[mt] = (uint32_t)(krl * TPS * 4 + (wm + mt * 16 + mcl) * 2);
        } else {
            const int arl = (lane & 7) + (lane & 8);
            const int awd = (lane & 16) ? 4 : 0;
            #pragma unroll
            for (int mt = 0; mt < 4; mt++)
                aoff[mt] = (uint32_t)(((wm + mt * 16 + arl) * APS + awd) * 4);
        }
        const int brl = lane & 7;
        const int bwd = BSINGLE ? (((lane >> 3) & 1) * 4)
                                : (((lane >> 3) & 3) * 4);
        #pragma unroll
        for (int nt = 0; nt < 4; nt++)
            boff[nt] = (uint32_t)(((wn + nt * 8 + brl) * BPS + bwd) * 4);
    }

    // In-kernel softmax scale computation (replaces combine_stats kernel):
    // this CTA's B rows are i = n0..n0+127; scale[i][blk] = exp(lmax-M)/S.
    if (BSCALE) {
        if (tid < 128) {
            const size_t base = ((size_t)bz * NP + n0 + tid) * NBLK;
            float lm[NBLK];
            float M = -FLT_MAX;
            #pragma unroll
            for (int j = 0; j < NBLK; j++) {
                lm[j] = lmax_io[base + j];
                M = fmaxf(M, lm[j]);
            }
            float S = 0.f;
            #pragma unroll
            for (int j = 0; j < NBLK; j++) {
                lm[j] = __expf(lm[j] - M);
                S += lsum_io[base + j] * lm[j];
            }
            const float inv = 1.0f / S;
            #pragma unroll
            for (int j = 0; j < NBLK; j++)
                sscale[tid * NBLK + j] = lm[j] * inv;
        }
    }

    float acc[4][4][4];
    #pragma unroll
    for (int mt = 0; mt < 4; mt++)
        #pragma unroll
        for (int nt = 0; nt < 4; nt++)
            #pragma unroll
            for (int r = 0; r < 4; r++) acc[mt][nt][r] = 0.f;

    const int nk = Ktot / KC;

    // issue cp.async loads for one chunk into stage s (AMODE 0/1 + B)
    auto issue_loads = [&](int chunk, int s) {
        const int k0 = chunk * KC;
        if (AMODE != 2 && aload) {
            const uint32_t ad = aS + (uint32_t)s * stageA + sdstA;
            cpasync16(ad,      Asrc + k0);
            cpasync16(ad + 16, Asrc + k0 + 8);
        }
        if (bload) {
            const uint32_t bd = bS + (uint32_t)s * stageB + sdstB;
            cpasync16(bd,      Bsrc + k0);
            cpasync16(bd + 16, Bsrc + k0 + 8);
        }
        CP_COMMIT();
    };

    // T-layout STS helper for AMODE2
    auto sts_trans = [&](int s, float4 v0, float4 v1) {
        uint32_t h[4], l[4];
        split_pair_words(v0.x, v0.y, h[0], l[0]);
        split_pair_words(v0.z, v0.w, h[1], l[1]);
        split_pair_words(v1.x, v1.y, h[2], l[2]);
        split_pair_words(v1.z, v1.w, h[3], l[3]);
        uint32_t* hp = Asm + s * ASTAGE + (sdstT >> 2);
        *(uint4*)hp              = make_uint4(h[0], h[1], h[2], h[3]);
        *(uint4*)(hp + KC * TPS) = make_uint4(l[0], l[1], l[2], l[3]);
    };

    // per-chunk compute on stage buffers (ab, bb = byte bases)
    auto compute_chunk = [&](int kb, uint32_t ab, uint32_t bb) {
        uint32_t ah[4][4], al[4][4];
        #pragma unroll
        for (int mt = 0; mt < 4; mt++) {
            if (AMODE == 2) {
                ldsm4t(ah[mt], ab + aoff[mt]);
                ldsm4t(al[mt], ab + aoff[mt] + KC * TPS * 4);
            } else {
                ldsm4(ah[mt], ab + aoff[mt]);
                if (AMODE == 0)
                    ldsm4(al[mt], ab + aoff[mt] + 32);
            }
        }
        #pragma unroll
        for (int nt = 0; nt < 4; nt++) {
            if (BSINGLE) {
                uint32_t bv[2];
                ldsm2(bv, bb + boff[nt]);
                if (BSCALE) {
                    const float s = sscale[(wn + nt * 8 + (lane >> 2)) * NBLK + (kb >> 3)];
                    const __half2 hs = __float2half2_rn(s);
                    *(__half2*)&bv[0] = __hmul2(*(const __half2*)&bv[0], hs);
                    *(__half2*)&bv[1] = __hmul2(*(const __half2*)&bv[1], hs);
                }
                if (AMODE != 1) {
                    #pragma unroll
                    for (int mt = 0; mt < 4; mt++)
                        mma_f16(acc[mt][nt], al[mt], bv[0], bv[1]);
                }
                #pragma unroll
                for (int mt = 0; mt < 4; mt++)
                    mma_f16(acc[mt][nt], ah[mt], bv[0], bv[1]);
            } else {
                uint32_t bv[4];
                ldsm4(bv, bb + boff[nt]);
                if (AMODE != 1) {
                    #pragma unroll
                    for (int mt = 0; mt < 4; mt++)
                        mma_f16(acc[mt][nt], ah[mt], bv[2], bv[3]);   // ah*bl
                    #pragma unroll
                    for (int mt = 0; mt < 4; mt++)
                        mma_f16(acc[mt][nt], al[mt], bv[0], bv[1]);   // al*bh
                    #pragma unroll
                    for (int mt = 0; mt < 4; mt++)
                        mma_f16(acc[mt][nt], ah[mt], bv[0], bv[1]);   // ah*bh
                } else {
                    #pragma unroll
                    for (int mt = 0; mt < 4; mt++)
                        mma_f16(acc[mt][nt], ah[mt], bv[2], bv[3]);
                    #pragma unroll
                    for (int mt = 0; mt < 4; mt++)
                        mma_f16(acc[mt][nt], ah[mt], bv[0], bv[1]);
                }
            }
        }
    };

    if (STAGES == 2) {
        // ---- AMODE2: 2-stage, register-staged fp32 A transpose + cp.async B
        {
            float4 v0 = *(const float4*)Ag;
            float4 v1 = *(const float4*)(Ag + 4);
            sts_trans(0, v0, v1);
            issue_loads(0, 0);
            CP_WAIT0();
            __syncthreads();
        }
        int buf = 0;
        for (int kb = 0; kb < nk; kb++) {
            const bool has_next = (kb + 1) < nk;
            float4 av0, av1;
            if (has_next) {
                const float* p = Ag + (size_t)(kb + 1) * KC * lda;
                av0 = *(const float4*)p;
                av1 = *(const float4*)(p + 4);
                issue_loads(kb + 1, buf ^ 1);
            }
            compute_chunk(kb, aS + buf * stageA, bS + buf * stageB);
            if (has_next) {
                sts_trans(buf ^ 1, av0, av1);
                CP_WAIT0();
                __syncthreads();
                buf ^= 1;
            }
        }
    } else {
        // ---- AMODE 0/1: 3-stage cp.async ring, wait_group 1
        issue_loads(0, 0);
        if (nk > 1) issue_loads(1, 1);
        for (int kb = 0; kb < nk; kb++) {
            if (kb + 1 < nk) { CP_WAIT1(); } else { CP_WAIT0(); }
            __syncthreads();
            if (kb + 2 < nk) issue_loads(kb + 2, (kb + 2) % 3);
            const int s = kb % 3;
            compute_chunk(kb, aS + s * stageA, bS + s * stageB);
        }
    }

    // ---- epilogue ----
    if (OMODE == 2) {
        const int wni = wid >> 1;
        float rmax[8];
        #pragma unroll
        for (int j = 0; j < 8; j++) rmax[j] = -FLT_MAX;
        #pragma unroll
        for (int mt = 0; mt < 4; mt++)
            #pragma unroll
            for (int nt = 0; nt < 4; nt++) {
                rmax[mt * 2 + 0] = fmaxf(rmax[mt * 2 + 0],
                                         fmaxf(acc[mt][nt][0], acc[mt][nt][1]));
                rmax[mt * 2 + 1] = fmaxf(rmax[mt * 2 + 1],
                                         fmaxf(acc[mt][nt][2], acc[mt][nt][3]));
            }
        #pragma unroll
        for (int j = 0; j < 8; j++) {
            rmax[j] = fmaxf(rmax[j], __shfl_xor_sync(0xffffffffu, rmax[j], 1));
            rmax[j] = fmaxf(rmax[j], __shfl_xor_sync(0xffffffffu, rmax[j], 2));
        }
        if (qc == 0)
            #pragma unroll
            for (int mt = 0; mt < 4; mt++)
                #pragma unroll
                for (int h = 0; h < 2; h++)
                    red[wni][wm + mt * 16 + qr + 8 * h] = rmax[mt * 2 + h];
        __syncthreads();
        float fm[8];
        #pragma unroll
        for (int mt = 0; mt < 4; mt++)
            #pragma unroll
            for (int h = 0; h < 2; h++) {
                const int rl = wm + mt * 16 + qr + 8 * h;
                fm[mt * 2 + h] = fmaxf(fmaxf(red[0][rl], red[1][rl]),
                                       fmaxf(red[2][rl], red[3][rl]));
            }
        __syncthreads();

        float rs[8];
        #pragma unroll
        for (int j = 0; j < 8; j++) rs[j] = 0.f;
        uint32_t* chb = Chi + (size_t)bz * (sC >> 1);
        #pragma unroll
        for (int mt = 0; mt < 4; mt++)
            #pragma unroll
            for (int nt = 0; nt < 4; nt++) {
                const int col = n0 + wn + nt * 8 + 2 * qc;
                #pragma unroll
                for (int h = 0; h < 2; h++) {
                    const float e0 = __expf(acc[mt][nt][2 * h + 0] - fm[mt * 2 + h]);
                    const float e1 = __expf(acc[mt][nt][2 * h + 1] - fm[mt * 2 + h]);
                    const int row = m0 + wm + mt * 16 + qr + 8 * h;
                    chb[(size_t)row * (ldc >> 1) + (col >> 1)] = pack_h2(e0, e1);
                    rs[mt * 2 + h] += e0 + e1;
                }
            }
        #pragma unroll
        for (int j = 0; j < 8; j++) {
            rs[j] += __shfl_xor_sync(0xffffffffu, rs[j], 1);
            rs[j] += __shfl_xor_sync(0xffffffffu, rs[j], 2);
        }
        if (qc == 0)
            #pragma unroll
            for (int mt = 0; mt < 4; mt++)
                #pragma unroll
                for (int h = 0; h < 2; h++)
                    red[wni][wm + mt * 16 + qr + 8 * h] = rs[mt * 2 + h];
        __syncthreads();
        if (wni == 0 && qc == 0) {
            #pragma unroll
            for (int mt = 0; mt < 4; mt++)
                #pragma unroll
                for (int h = 0; h < 2; h++) {
                    const int rl = wm + mt * 16 + qr + 8 * h;
                    const float sm = red[0][rl] + red[1][rl] + red[2][rl] + red[3][rl];
                    const size_t o = ((size_t)bz * NP + m0 + rl) * NBLK + blockIdx.y;
                    lmax_io[o] = fm[mt * 2 + h];
                    lsum_io[o] = sm;
                }
        }
    } else {
        #pragma unroll
        for (int mt = 0; mt < 4; mt++) {
            #pragma unroll
            for (int nt = 0; nt < 4; nt++) {
                const int row = m0 + wm + mt * 16 + qr;
                const int col = n0 + wn + nt * 8 + 2 * qc;
                float v0 = acc[mt][nt][0], v1 = acc[mt][nt][1];
                float v2 = acc[mt][nt][2], v3 = acc[mt][nt][3];
                if (BIAS) {
                    const float b0 = bias[col], b1 = bias[col + 1];
                    v0 += b0; v1 += b1; v2 += b0; v3 += b1;
                }
                if (OMODE == 1) {
                    uint32_t* chb = Chi + (size_t)bz * (sC >> 1);
                    uint32_t* clb = Clo + (size_t)bz * (sC >> 1);
                    uint32_t hw, lw;
                    split_pair_words(v0, v1, hw, lw);
                    size_t o = (size_t)row * (ldc >> 1) + (col >> 1);
                    chb[o] = hw; clb[o] = lw;
                    split_pair_words(v2, v3, hw, lw);
                    o = (size_t)(row + 8) * (ldc >> 1) + (col >> 1);
                    chb[o] = hw; clb[o] = lw;
                } else {
                    float* cb = C + sC * bz;
                    *(float2*)&cb[(size_t)row * ldc + col]       = make_float2(v0, v1);
                    *(float2*)&cb[(size_t)(row + 8) * ldc + col] = make_float2(v2, v3);
                }
            }
        }
    }
}

// ---------------------------------------------------------------------------
extern "C" void kernel_launch(void* const* d_in, const int* in_sizes, int n_in,
                              void* d_out, int out_size)
{
    const float* qf = (const float*)d_in[0];   // [B, CQ, 48, 48]
    const float* rf = (const float*)d_in[1];   // [B, CR, 48, 48]
    const float* Wq = (const float*)d_in[2];   // [HID, CQ]
    const float* bq = (const float*)d_in[3];   // [HID]
    const float* Wk = (const float*)d_in[4];   // [HID, CR]
    const float* bk = (const float*)d_in[5];   // [HID]
    float* out = (float*)d_out;                // [B, CR, 48, 48]

    uint32_t *rfS, *Wqh, *Wql, *Wkh, *Wkl, *Qh, *Ql, *Kh, *Kl, *ath;
    float *lmx, *lsm;
    cudaGetSymbolAddress((void**)&rfS, g_rfS);
    cudaGetSymbolAddress((void**)&Wqh, g_Wq_hi);
    cudaGetSymbolAddress((void**)&Wql, g_Wq_lo);
    cudaGetSymbolAddress((void**)&Wkh, g_Wk_hi);
    cudaGetSymbolAddress((void**)&Wkl, g_Wk_lo);
    cudaGetSymbolAddress((void**)&Qh, g_Q_hi);
    cudaGetSymbolAddress((void**)&Ql, g_Q_lo);
    cudaGetSymbolAddress((void**)&Kh, g_K_hi);
    cudaGetSymbolAddress((void**)&Kl, g_K_lo);
    cudaGetSymbolAddress((void**)&ath, g_at);
    cudaGetSymbolAddress((void**)&lmx, g_lmax);
    cudaGetSymbolAddress((void**)&lsm, g_lsum);

    // dynamic smem sizes (bytes) for 3-stage AMODE 0/1 kernels
    const int smem3 = (3 * (128 * 20) * 2) * 4;                    // 61440
    const int smem4 = (3 * (128 * 12) * 2) * 4;                    // 36864
    cudaFuncSetAttribute(bgemm<false, 2, 0, false, false>,
                         cudaFuncAttributeMaxDynamicSharedMemorySize, smem3);
    cudaFuncSetAttribute(bgemm<false, 0, 1, true, true>,
                         cudaFuncAttributeMaxDynamicSharedMemorySize, smem4);

    // ---- prepass: weight splits + V convert ----
    {
        size_t np;
        np = (size_t)HID * CQ / 2;
        split_pairs<<<(unsigned)((np + 255) / 256), 256>>>(Wq, Wqh, Wql, np);
        np = (size_t)HID * CR / 2;
        split_pairs<<<(unsigned)((np + 255) / 256), 256>>>(Wk, Wkh, Wkl, np);
        np = (size_t)BB * CR * NP / 2;
        cvt_pairs<<<(unsigned)((np + 255) / 256), 256>>>(rf, rfS, np);
    }

    // ---- GEMM1: Q[i][o] = qf[c][i] * Wq[o][c] + bq (fused transpose A,
    //      2-stage static smem — R14 config) ----
    bgemm<true, 1, 2, false, false><<<dim3(NP / 128, HID / 128, BB), 256>>>(
        (const uint32_t*)qf, nullptr, NP, (size_t)CQ * NP,
        Wqh, Wql, CQ, 0,
        bq,
        nullptr, Qh, Ql, HID, (size_t)NP * HID,
        CQ, nullptr, nullptr);

    // ---- GEMM2: K[p][o] = rf[c][p] * Wk[o][c] + bk ----
    bgemm<true, 1, 2, false, false><<<dim3(NP / 128, HID / 128, BB), 256>>>(
        (const uint32_t*)rf, nullptr, NP, (size_t)CR * NP,
        Wkh, Wkl, CR, 0,
        bk,
        nullptr, Kh, Kl, HID, (size_t)NP * HID,
        CR, nullptr, nullptr);

    // ---- GEMM3: S[i][p] = Q[i][k] * K[p][k]; flash epilogue (3-stage) ----
    bgemm<false, 2, 0, false, false><<<dim3(NP / 128, NP / 128, BB), 256, smem3>>>(
        Qh, Ql, HID, (size_t)NP * HID,
        Kh, Kl, HID, (size_t)NP * HID,
        nullptr,
        nullptr, ath, nullptr, NP, (size_t)NP * NP,
        HID, lmx, lsm);

    // ---- GEMM4: out[c][i] = V[c][p] * exp[i][p] * scale[i][blk(p)];
    //      scales computed in-kernel from (lmax, lsum); 3-stage ----
    bgemm<false, 0, 1, true, true><<<dim3(CR / 128, NP / 128, BB), 256, smem4>>>(
        rfS, rfS, NP, (size_t)CR * NP,
        ath, ath, NP, (size_t)NP * NP,
        nullptr,
        out, nullptr, nullptr, NP, (size_t)CR * NP,
        NP, lmx, lsm);
}

// round 17
// speedup vs baseline: 1.0141x; 1.0002x over previous
#include <cuda_runtime.h>
#include <cuda_fp16.h>
#include <math.h>
#include <float.h>
#include <stdint.h>

// Problem constants
#define BB   8
#define CQ   1024
#define CR   512
#define HID  256
#define NP   2304          // H*W = 48*48
#define NBLK 18            // NP / 128 p-blocks

#define KC   16            // k per smem stage
#define TPS  68            // T-layout smem words per k-row (64 data + 4 pad)

// ---------------------------------------------------------------------------
// Device-global scratch. "Planes" are fp16 hi/lo pairs packed in u32.
// ---------------------------------------------------------------------------
__device__ uint32_t g_rfS[(size_t)BB * CR * NP / 2];      // [b][c][p] V, single fp16
__device__ uint32_t g_Wq_hi[(size_t)HID * CQ / 2];
__device__ uint32_t g_Wq_lo[(size_t)HID * CQ / 2];
__device__ uint32_t g_Wk_hi[(size_t)HID * CR / 2];
__device__ uint32_t g_Wk_lo[(size_t)HID * CR / 2];
__device__ uint32_t g_Q_hi[(size_t)BB * NP * HID / 2];    // [b][i][o]
__device__ uint32_t g_Q_lo[(size_t)BB * NP * HID / 2];
__device__ uint32_t g_K_hi[(size_t)BB * NP * HID / 2];    // [b][p][o]
__device__ uint32_t g_K_lo[(size_t)BB * NP * HID / 2];
__device__ uint32_t g_at[(size_t)BB * NP * NP / 2];       // [b][i][p] exp(x-lmax), fp16
__device__ float    g_lmax[(size_t)BB * NP * NBLK];       // per (row, p-block) max
__device__ float    g_lsum[(size_t)BB * NP * NBLK];       // per (row, p-block) sum

// ---------------------------------------------------------------------------
// helpers
// ---------------------------------------------------------------------------
__device__ __forceinline__ void split_f16(float x, unsigned short &h, unsigned short &l) {
    __half hb = __float2half_rn(x);
    h = __half_as_ushort(hb);
    float r = x - __half2float(hb);
    l = __half_as_ushort(__float2half_rn(r));
}
__device__ __forceinline__ void split_pair_words(float x0, float x1,
                                                 uint32_t &hw, uint32_t &lw) {
    unsigned short h0, l0, h1, l1;
    split_f16(x0, h0, l0);
    split_f16(x1, h1, l1);
    hw = (uint32_t)h0 | ((uint32_t)h1 << 16);
    lw = (uint32_t)l0 | ((uint32_t)l1 << 16);
}
__device__ __forceinline__ uint32_t pack_h2(float x0, float x1) {
    const __half2 h2 = __floats2half2_rn(x0, x1);
    return *(const uint32_t*)&h2;
}

// fp16 inputs, fp32 accumulate
__device__ __forceinline__ void mma_f16(float c[4], const uint32_t a[4],
                                        const uint32_t b0, const uint32_t b1) {
    asm volatile(
        "mma.sync.aligned.m16n8k16.row.col.f32.f16.f16.f32 "
        "{%0,%1,%2,%3}, {%4,%5,%6,%7}, {%8,%9}, {%0,%1,%2,%3};\n"
        : "+f"(c[0]), "+f"(c[1]), "+f"(c[2]), "+f"(c[3])
        : "r"(a[0]), "r"(a[1]), "r"(a[2]), "r"(a[3]),
          "r"(b0), "r"(b1));
}

__device__ __forceinline__ void ldsm4(uint32_t r[4], uint32_t addr) {
    asm volatile("ldmatrix.sync.aligned.m8n8.x4.shared.b16 {%0,%1,%2,%3}, [%4];"
                 : "=r"(r[0]), "=r"(r[1]), "=r"(r[2]), "=r"(r[3]) : "r"(addr));
}
__device__ __forceinline__ void ldsm4t(uint32_t r[4], uint32_t addr) {
    asm volatile("ldmatrix.sync.aligned.m8n8.x4.trans.shared.b16 {%0,%1,%2,%3}, [%4];"
                 : "=r"(r[0]), "=r"(r[1]), "=r"(r[2]), "=r"(r[3]) : "r"(addr));
}
__device__ __forceinline__ void ldsm2(uint32_t r[2], uint32_t addr) {
    asm volatile("ldmatrix.sync.aligned.m8n8.x2.shared.b16 {%0,%1}, [%2];"
                 : "=r"(r[0]), "=r"(r[1]) : "r"(addr));
}
__device__ __forceinline__ void cpasync16(uint32_t saddr, const void* g) {
    asm volatile("cp.async.cg.shared.global [%0], [%1], 16;" :: "r"(saddr), "l"(g));
}
#define CP_COMMIT() asm volatile("cp.async.commit_group;" ::: "memory")
#define CP_WAIT0()  asm volatile("cp.async.wait_group 0;" ::: "memory")
#define CP_WAIT1()  asm volatile("cp.async.wait_group 1;" ::: "memory")

// ---------------------------------------------------------------------------
// Elementwise split: fp32 -> hi/lo fp16 planes (pairs packed in u32).
// ---------------------------------------------------------------------------
__global__ void __launch_bounds__(256) split_pairs(
    const float* __restrict__ src,
    uint32_t* __restrict__ dhi, uint32_t* __restrict__ dlo, size_t npairs)
{
    size_t i = (size_t)blockIdx.x * 256 + threadIdx.x;
    if (i >= npairs) return;
    uint32_t hw, lw;
    split_pair_words(src[2 * i], src[2 * i + 1], hw, lw);
    dhi[i] = hw;
    dlo[i] = lw;
}

// ---------------------------------------------------------------------------
// Elementwise convert: fp32 -> single fp16 plane (pairs packed in u32).
// ---------------------------------------------------------------------------
__global__ void __launch_bounds__(256) cvt_pairs(
    const float* __restrict__ src,
    uint32_t* __restrict__ dst, size_t npairs)
{
    size_t i = (size_t)blockIdx.x * 256 + threadIdx.x;
    if (i >= npairs) return;
    dst[i] = pack_h2(src[2 * i], src[2 * i + 1]);
}

// ---------------------------------------------------------------------------
// Split-fp16 tensor-core GEMM.
//   C[m][n] = sum_k A[m][k] * B[n][k]
// 128x128 CTA tile, 256 threads, 8 warps = 2(m) x 4(n), warp tile 64x32.
// AMODE: 0 = A hi/lo planes R-layout (3-stage cp.async ring, dynamic smem),
//        1 = A single plane R-layout (3-stage ring, dynamic smem),
//        2 = A fp32 [k][m] source (fused transpose+split), 2-chunk register
//            prefetch on A + 2-stage A smem + 3-stage cp.async B ring,
//            static smem (48128 B).
// BSINGLE: B single fp16 plane. OMODE: 0 fp32 / 1 split / 2 flash softmax.
// BSCALE: softmax scales computed IN-KERNEL from lmax/lsum stats.
// ---------------------------------------------------------------------------
template<bool BIAS, int OMODE, int AMODE, bool BSINGLE, bool BSCALE>
__global__ void __launch_bounds__(256, 2) bgemm(
    const uint32_t* __restrict__ Ahi32, const uint32_t* __restrict__ Alo32,
    int lda, size_t sA,
    const uint32_t* __restrict__ Bhi32, const uint32_t* __restrict__ Blo32,
    int ldb, size_t sB,
    const float* __restrict__ bias,
    float* __restrict__ C, uint32_t* __restrict__ Chi, uint32_t* __restrict__ Clo,
    int ldc, size_t sC, int Ktot,
    float* __restrict__ lmax_io, float* __restrict__ lsum_io)
{
    constexpr int ASTAGES = (AMODE == 2) ? 2 : 3;
    constexpr int BSTAGES = 3;
    constexpr int ASTAGE = (AMODE == 2) ? (2 * KC * TPS)
                         : (AMODE == 1) ? (128 * 12) : (128 * 20);
    constexpr int BPS = BSINGLE ? 12 : 20;
    constexpr int BSTAGE = 128 * BPS;

    // AMODE2 uses static smem; AMODE 0/1 use dynamic smem.
    __shared__ uint32_t Ast[(AMODE == 2) ? (ASTAGES * ASTAGE) : 1];
    __shared__ uint32_t Bst[(AMODE == 2) ? (BSTAGES * BSTAGE) : 1];
    extern __shared__ uint32_t dsm[];
    uint32_t* Asm = (AMODE == 2) ? Ast : dsm;
    uint32_t* Bsm = (AMODE == 2) ? Bst : (dsm + ASTAGES * ASTAGE);
    __shared__ float red[OMODE == 2 ? 4 : 1][OMODE == 2 ? 128 : 1];
    __shared__ float sscale[BSCALE ? 128 * NBLK : 1];

    const int bz = blockIdx.z;
    const int tid = threadIdx.x;
    const int m0  = blockIdx.x * 128;
    const int n0  = blockIdx.y * 128;

    // ---- B loader (cp.async): thread -> (row, plane); 2x16B per plane/stage
    const __half* Bhi = (const __half*)Bhi32 + sB * bz;
    const __half* Blo = (const __half*)Blo32 + sB * bz;
    const int lrow = tid >> 1;
    const int lpl  = tid & 1;
    const __half* Bsrc = ((lpl && !BSINGLE) ? Blo : Bhi) + (size_t)(n0 + lrow) * ldb;
    const bool   bload = (!BSINGLE) || (lpl == 0);
    const uint32_t sdstB = (uint32_t)(lrow * BPS + lpl * 8) * 4;

    // ---- A loader ----
    const __half* Ahi = (const __half*)Ahi32 + sA * bz;
    const __half* Alo = (const __half*)Alo32 + sA * bz;
    const __half* Asrc = ((lpl && AMODE == 0) ? Alo : Ahi) + (size_t)(m0 + lrow) * lda;
    const bool   aload = (AMODE == 0) || (lpl == 0);
    constexpr int APS = (AMODE == 1) ? 12 : 20;
    const uint32_t sdstA = (uint32_t)(lrow * APS + lpl * 8) * 4;
    // AMODE 2 (fp32 [k][m] LDG + split)
    const float* Af = (const float*)Ahi32 + sA * bz;
    const int tkr = tid >> 4;
    const int tmc = (tid & 15) * 8;
    const float* Ag = Af + (size_t)tkr * lda + m0 + tmc;
    const uint32_t sdstT = (uint32_t)(tkr * TPS + (tid & 15) * 4) * 4;

    const uint32_t aS = (uint32_t)__cvta_generic_to_shared(Asm);
    const uint32_t bS = (uint32_t)__cvta_generic_to_shared(Bsm);
    const uint32_t stageA = ASTAGE * 4;
    const uint32_t stageB = BSTAGE * 4;

    // warp/lane decomposition
    const int wid = tid >> 5, lane = tid & 31;
    const int wm = (wid & 1) * 64;
    const int wn = (wid >> 1) * 32;
    const int qr = lane >> 2, qc = lane & 3;

    // ldmatrix per-lane addresses (byte offsets within a stage)
    uint32_t aoff[4], boff[4];
    {
        if (AMODE == 2) {
            const int krl = (lane & 7) + ((lane & 16) ? 8 : 0);
            const int mcl = (lane & 8) ? 8 : 0;
            #pragma unroll
            for (int mt = 0; mt < 4; mt++)
                aoff[mt] = (uint32_t)(krl * TPS * 4 + (wm + mt * 16 + mcl) * 2);
        } else {
            const int arl = (lane & 7) + (lane & 8);
            const int awd = (lane & 16) ? 4 : 0;
            #pragma unroll
            for (int mt = 0; mt < 4; mt++)
                aoff[mt] = (uint32_t)(((wm + mt * 16 + arl) * APS + awd) * 4);
        }
        const int brl = lane & 7;
        const int bwd = BSINGLE ? (((lane >> 3) & 1) * 4)
                                : (((lane >> 3) & 3) * 4);
        #pragma unroll
        for (int nt = 0; nt < 4; nt++)
            boff[nt] = (uint32_t)(((wn + nt * 8 + brl) * BPS + bwd) * 4);
    }

    // In-kernel softmax scale computation: this CTA's B rows are i = n0..n0+127.
    if (BSCALE) {
        if (tid < 128) {
            const size_t base = ((size_t)bz * NP + n0 + tid) * NBLK;
            float lm[NBLK];
            float M = -FLT_MAX;
            #pragma unroll
            for (int j = 0; j < NBLK; j++) {
                lm[j] = lmax_io[base + j];
                M = fmaxf(M, lm[j]);
            }
            float S = 0.f;
            #pragma unroll
            for (int j = 0; j < NBLK; j++) {
                lm[j] = __expf(lm[j] - M);
                S += lsum_io[base + j] * lm[j];
            }
            const float inv = 1.0f / S;
            #pragma unroll
            for (int j = 0; j < NBLK; j++)
                sscale[tid * NBLK + j] = lm[j] * inv;
        }
    }

    float acc[4][4][4];
    #pragma unroll
    for (int mt = 0; mt < 4; mt++)
        #pragma unroll
        for (int nt = 0; nt < 4; nt++)
            #pragma unroll
            for (int r = 0; r < 4; r++) acc[mt][nt][r] = 0.f;

    const int nk = Ktot / KC;

    // issue cp.async loads for one chunk into stage s (AMODE 0/1 A + B)
    auto issue_loads = [&](int chunk, int s) {
        const int k0 = chunk * KC;
        if (AMODE != 2 && aload) {
            const uint32_t ad = aS + (uint32_t)s * stageA + sdstA;
            cpasync16(ad,      Asrc + k0);
            cpasync16(ad + 16, Asrc + k0 + 8);
        }
        if (bload) {
            const uint32_t bd = bS + (uint32_t)s * stageB + sdstB;
            cpasync16(bd,      Bsrc + k0);
            cpasync16(bd + 16, Bsrc + k0 + 8);
        }
        CP_COMMIT();
    };

    // T-layout STS helper for AMODE2
    auto sts_trans = [&](int s, float4 v0, float4 v1) {
        uint32_t h[4], l[4];
        split_pair_words(v0.x, v0.y, h[0], l[0]);
        split_pair_words(v0.z, v0.w, h[1], l[1]);
        split_pair_words(v1.x, v1.y, h[2], l[2]);
        split_pair_words(v1.z, v1.w, h[3], l[3]);
        uint32_t* hp = Asm + s * ASTAGE + (sdstT >> 2);
        *(uint4*)hp              = make_uint4(h[0], h[1], h[2], h[3]);
        *(uint4*)(hp + KC * TPS) = make_uint4(l[0], l[1], l[2], l[3]);
    };

    // per-chunk compute on stage buffers (ab, bb = byte bases)
    auto compute_chunk = [&](int kb, uint32_t ab, uint32_t bb) {
        uint32_t ah[4][4], al[4][4];
        #pragma unroll
        for (int mt = 0; mt < 4; mt++) {
            if (AMODE == 2) {
                ldsm4t(ah[mt], ab + aoff[mt]);
                ldsm4t(al[mt], ab + aoff[mt] + KC * TPS * 4);
            } else {
                ldsm4(ah[mt], ab + aoff[mt]);
                if (AMODE == 0)
                    ldsm4(al[mt], ab + aoff[mt] + 32);
            }
        }
        #pragma unroll
        for (int nt = 0; nt < 4; nt++) {
            if (BSINGLE) {
                uint32_t bv[2];
                ldsm2(bv, bb + boff[nt]);
                if (BSCALE) {
                    const float s = sscale[(wn + nt * 8 + (lane >> 2)) * NBLK + (kb >> 3)];
                    const __half2 hs = __float2half2_rn(s);
                    *(__half2*)&bv[0] = __hmul2(*(const __half2*)&bv[0], hs);
                    *(__half2*)&bv[1] = __hmul2(*(const __half2*)&bv[1], hs);
                }
                if (AMODE != 1) {
                    #pragma unroll
                    for (int mt = 0; mt < 4; mt++)
                        mma_f16(acc[mt][nt], al[mt], bv[0], bv[1]);
                }
                #pragma unroll
                for (int mt = 0; mt < 4; mt++)
                    mma_f16(acc[mt][nt], ah[mt], bv[0], bv[1]);
            } else {
                uint32_t bv[4];
                ldsm4(bv, bb + boff[nt]);
                if (AMODE != 1) {
                    #pragma unroll
                    for (int mt = 0; mt < 4; mt++)
                        mma_f16(acc[mt][nt], ah[mt], bv[2], bv[3]);   // ah*bl
                    #pragma unroll
                    for (int mt = 0; mt < 4; mt++)
                        mma_f16(acc[mt][nt], al[mt], bv[0], bv[1]);   // al*bh
                    #pragma unroll
                    for (int mt = 0; mt < 4; mt++)
                        mma_f16(acc[mt][nt], ah[mt], bv[0], bv[1]);   // ah*bh
                } else {
                    #pragma unroll
                    for (int mt = 0; mt < 4; mt++)
                        mma_f16(acc[mt][nt], ah[mt], bv[2], bv[3]);
                    #pragma unroll
                    for (int mt = 0; mt < 4; mt++)
                        mma_f16(acc[mt][nt], ah[mt], bv[0], bv[1]);
                }
            }
        }
    };

    if (AMODE == 2) {
        // ---- A: 2-chunk register prefetch + 2-stage smem; B: 3-stage ring
        {
            float4 c0a = *(const float4*)Ag;
            float4 c0b = *(const float4*)(Ag + 4);
            sts_trans(0, c0a, c0b);
            issue_loads(0, 0);
        }
        float4 r1a, r1b;
        if (nk > 1) {
            const float* p = Ag + (size_t)KC * lda;
            r1a = *(const float4*)p;
            r1b = *(const float4*)(p + 4);
            issue_loads(1, 1);
        }
        if (nk > 1) { CP_WAIT1(); } else { CP_WAIT0(); }
        __syncthreads();

        for (int kb = 0; kb < nk; kb++) {
            float4 r2a, r2b;
            if (kb + 2 < nk) {
                const float* p = Ag + (size_t)(kb + 2) * KC * lda;
                r2a = *(const float4*)p;
                r2b = *(const float4*)(p + 4);
                issue_loads(kb + 2, (kb + 2) % 3);
            }
            if (kb + 1 < nk)
                sts_trans((kb + 1) & 1, r1a, r1b);   // stage (kb-1)&1: drained
            compute_chunk(kb, aS + (kb & 1) * stageA, bS + (kb % 3) * stageB);
            if (kb + 1 < nk) {
                if (kb + 2 < nk) { CP_WAIT1(); } else { CP_WAIT0(); }
                __syncthreads();
                r1a = r2a; r1b = r2b;
            }
        }
    } else {
        // ---- AMODE 0/1: 3-stage cp.async ring, wait_group 1
        issue_loads(0, 0);
        if (nk > 1) issue_loads(1, 1);
        for (int kb = 0; kb < nk; kb++) {
            if (kb + 1 < nk) { CP_WAIT1(); } else { CP_WAIT0(); }
            __syncthreads();
            if (kb + 2 < nk) issue_loads(kb + 2, (kb + 2) % 3);
            const int s = kb % 3;
            compute_chunk(kb, aS + s * stageA, bS + s * stageB);
        }
    }

    // ---- epilogue ----
    if (OMODE == 2) {
        const int wni = wid >> 1;
        float rmax[8];
        #pragma unroll
        for (int j = 0; j < 8; j++) rmax[j] = -FLT_MAX;
        #pragma unroll
        for (int mt = 0; mt < 4; mt++)
            #pragma unroll
            for (int nt = 0; nt < 4; nt++) {
                rmax[mt * 2 + 0] = fmaxf(rmax[mt * 2 + 0],
                                         fmaxf(acc[mt][nt][0], acc[mt][nt][1]));
                rmax[mt * 2 + 1] = fmaxf(rmax[mt * 2 + 1],
                                         fmaxf(acc[mt][nt][2], acc[mt][nt][3]));
            }
        #pragma unroll
        for (int j = 0; j < 8; j++) {
            rmax[j] = fmaxf(rmax[j], __shfl_xor_sync(0xffffffffu, rmax[j], 1));
            rmax[j] = fmaxf(rmax[j], __shfl_xor_sync(0xffffffffu, rmax[j], 2));
        }
        if (qc == 0)
            #pragma unroll
            for (int mt = 0; mt < 4; mt++)
                #pragma unroll
                for (int h = 0; h < 2; h++)
                    red[wni][wm + mt * 16 + qr + 8 * h] = rmax[mt * 2 + h];
        __syncthreads();
        float fm[8];
        #pragma unroll
        for (int mt = 0; mt < 4; mt++)
            #pragma unroll
            for (int h = 0; h < 2; h++) {
                const int rl = wm + mt * 16 + qr + 8 * h;
                fm[mt * 2 + h] = fmaxf(fmaxf(red[0][rl], red[1][rl]),
                                       fmaxf(red[2][rl], red[3][rl]));
            }
        __syncthreads();

        float rs[8];
        #pragma unroll
        for (int j = 0; j < 8; j++) rs[j] = 0.f;
        uint32_t* chb = Chi + (size_t)bz * (sC >> 1);
        #pragma unroll
        for (int mt = 0; mt < 4; mt++)
            #pragma unroll
            for (int nt = 0; nt < 4; nt++) {
                const int col = n0 + wn + nt * 8 + 2 * qc;
                #pragma unroll
                for (int h = 0; h < 2; h++) {
                    const float e0 = __expf(acc[mt][nt][2 * h + 0] - fm[mt * 2 + h]);
                    const float e1 = __expf(acc[mt][nt][2 * h + 1] - fm[mt * 2 + h]);
                    const int row = m0 + wm + mt * 16 + qr + 8 * h;
                    chb[(size_t)row * (ldc >> 1) + (col >> 1)] = pack_h2(e0, e1);
                    rs[mt * 2 + h] += e0 + e1;
                }
            }
        #pragma unroll
        for (int j = 0; j < 8; j++) {
            rs[j] += __shfl_xor_sync(0xffffffffu, rs[j], 1);
            rs[j] += __shfl_xor_sync(0xffffffffu, rs[j], 2);
        }
        if (qc == 0)
            #pragma unroll
            for (int mt = 0; mt < 4; mt++)
                #pragma unroll
                for (int h = 0; h < 2; h++)
                    red[wni][wm + mt * 16 + qr + 8 * h] = rs[mt * 2 + h];
        __syncthreads();
        if (wni == 0 && qc == 0) {
            #pragma unroll
            for (int mt = 0; mt < 4; mt++)
                #pragma unroll
                for (int h = 0; h < 2; h++) {
                    const int rl = wm + mt * 16 + qr + 8 * h;
                    const float sm = red[0][rl] + red[1][rl] + red[2][rl] + red[3][rl];
                    const size_t o = ((size_t)bz * NP + m0 + rl) * NBLK + blockIdx.y;
                    lmax_io[o] = fm[mt * 2 + h];
                    lsum_io[o] = sm;
                }
        }
    } else {
        #pragma unroll
        for (int mt = 0; mt < 4; mt++) {
            #pragma unroll
            for (int nt = 0; nt < 4; nt++) {
                const int row = m0 + wm + mt * 16 + qr;
                const int col = n0 + wn + nt * 8 + 2 * qc;
                float v0 = acc[mt][nt][0], v1 = acc[mt][nt][1];
                float v2 = acc[mt][nt][2], v3 = acc[mt][nt][3];
                if (BIAS) {
                    const float b0 = bias[col], b1 = bias[col + 1];
                    v0 += b0; v1 += b1; v2 += b0; v3 += b1;
                }
                if (OMODE == 1) {
                    uint32_t* chb = Chi + (size_t)bz * (sC >> 1);
                    uint32_t* clb = Clo + (size_t)bz * (sC >> 1);
                    uint32_t hw, lw;
                    split_pair_words(v0, v1, hw, lw);
                    size_t o = (size_t)row * (ldc >> 1) + (col >> 1);
                    chb[o] = hw; clb[o] = lw;
                    split_pair_words(v2, v3, hw, lw);
                    o = (size_t)(row + 8) * (ldc >> 1) + (col >> 1);
                    chb[o] = hw; clb[o] = lw;
                } else {
                    float* cb = C + sC * bz;
                    *(float2*)&cb[(size_t)row * ldc + col]       = make_float2(v0, v1);
                    *(float2*)&cb[(size_t)(row + 8) * ldc + col] = make_float2(v2, v3);
                }
            }
        }
    }
}

// ---------------------------------------------------------------------------
extern "C" void kernel_launch(void* const* d_in, const int* in_sizes, int n_in,
                              void* d_out, int out_size)
{
    const float* qf = (const float*)d_in[0];   // [B, CQ, 48, 48]
    const float* rf = (const float*)d_in[1];   // [B, CR, 48, 48]
    const float* Wq = (const float*)d_in[2];   // [HID, CQ]
    const float* bq = (const float*)d_in[3];   // [HID]
    const float* Wk = (const float*)d_in[4];   // [HID, CR]
    const float* bk = (const float*)d_in[5];   // [HID]
    float* out = (float*)d_out;                // [B, CR, 48, 48]

    uint32_t *rfS, *Wqh, *Wql, *Wkh, *Wkl, *Qh, *Ql, *Kh, *Kl, *ath;
    float *lmx, *lsm;
    cudaGetSymbolAddress((void**)&rfS, g_rfS);
    cudaGetSymbolAddress((void**)&Wqh, g_Wq_hi);
    cudaGetSymbolAddress((void**)&Wql, g_Wq_lo);
    cudaGetSymbolAddress((void**)&Wkh, g_Wk_hi);
    cudaGetSymbolAddress((void**)&Wkl, g_Wk_lo);
    cudaGetSymbolAddress((void**)&Qh, g_Q_hi);
    cudaGetSymbolAddress((void**)&Ql, g_Q_lo);
    cudaGetSymbolAddress((void**)&Kh, g_K_hi);
    cudaGetSymbolAddress((void**)&Kl, g_K_lo);
    cudaGetSymbolAddress((void**)&ath, g_at);
    cudaGetSymbolAddress((void**)&lmx, g_lmax);
    cudaGetSymbolAddress((void**)&lsm, g_lsum);

    // dynamic smem sizes (bytes) for 3-stage AMODE 0/1 kernels
    const int smem3 = (3 * (128 * 20) * 2) * 4;                    // 61440
    const int smem4 = (3 * (128 * 12) * 2) * 4;                    // 36864
    cudaFuncSetAttribute(bgemm<false, 2, 0, false, false>,
                         cudaFuncAttributeMaxDynamicSharedMemorySize, smem3);
    cudaFuncSetAttribute(bgemm<false, 0, 1, true, true>,
                         cudaFuncAttributeMaxDynamicSharedMemorySize, smem4);

    // ---- prepass: weight splits + V convert ----
    {
        size_t np;
        np = (size_t)HID * CQ / 2;
        split_pairs<<<(unsigned)((np + 255) / 256), 256>>>(Wq, Wqh, Wql, np);
        np = (size_t)HID * CR / 2;
        split_pairs<<<(unsigned)((np + 255) / 256), 256>>>(Wk, Wkh, Wkl, np);
        np = (size_t)BB * CR * NP / 2;
        cvt_pairs<<<(unsigned)((np + 255) / 256), 256>>>(rf, rfS, np);
    }

    // ---- GEMM1: Q[i][o] = qf[c][i] * Wq[o][c] + bq (fused transpose A,
    //      deep pipeline: 2-chunk A register prefetch + 3-stage B ring) ----
    bgemm<true, 1, 2, false, false><<<dim3(NP / 128, HID / 128, BB), 256>>>(
        (const uint32_t*)qf, nullptr, NP, (size_t)CQ * NP,
        Wqh, Wql, CQ, 0,
        bq,
        nullptr, Qh, Ql, HID, (size_t)NP * HID,
        CQ, nullptr, nullptr);

    // ---- GEMM2: K[p][o] = rf[c][p] * Wk[o][c] + bk ----
    bgemm<true, 1, 2, false, false><<<dim3(NP / 128, HID / 128, BB), 256>>>(
        (const uint32_t*)rf, nullptr, NP, (size_t)CR * NP,
        Wkh, Wkl, CR, 0,
        bk,
        nullptr, Kh, Kl, HID, (size_t)NP * HID,
        CR, nullptr, nullptr);

    // ---- GEMM3: S[i][p] = Q[i][k] * K[p][k]; flash epilogue (3-stage) ----
    bgemm<false, 2, 0, false, false><<<dim3(NP / 128, NP / 128, BB), 256, smem3>>>(
        Qh, Ql, HID, (size_t)NP * HID,
        Kh, Kl, HID, (size_t)NP * HID,
        nullptr,
        nullptr, ath, nullptr, NP, (size_t)NP * NP,
        HID, lmx, lsm);

    // ---- GEMM4: out[c][i] = V[c][p] * exp[i][p] * scale[i][blk(p)];
    //      scales computed in-kernel; 3-stage ----
    bgemm<false, 0, 1, true, true><<<dim3(CR / 128, NP / 128, BB), 256, smem4>>>(
        rfS, rfS, NP, (size_t)CR * NP,
        ath, ath, NP, (size_t)NP * NP,
        nullptr,
        out, nullptr, nullptr, NP, (size_t)CR * NP,
        NP, lmx, lsm);
}